// round 12
// baseline (speedup 1.0000x reference)
#include <cuda_runtime.h>
#include <cuda_fp16.h>
#include <cstdint>

static constexpr int BATCH    = 20000;
static constexpr int GRID     = 152;     // one persistent CTA per SM
static constexpr int NTHREADS = 512;     // 12 consumer warps + 4 producer warps
static constexpr int NCONS    = 384;

static constexpr int A_BYTES  = 65536;   // 8 K-chunks x 128 rows x 64B fp16 W tile
static constexpr int NSLOTS   = 6;
static constexpr int SLOT_BSZ = 12288;   // max NT(192) * 64B
static constexpr int MBAR_OFF = A_BYTES;             // 12 mbarriers (16B/slot pair)
static constexpr int SLOTS_OFF = A_BYTES + 128;
static constexpr int EPI_OFF  = SLOTS_OFF + NSLOTS * SLOT_BSZ;   // 139392
static constexpr int SMEM_BYTES = EPI_OFF + 50688;   // max epi (l0: 96*132*4)

__device__ __forceinline__ uint32_t smem_u32(const void* p) {
    uint32_t a;
    asm("{ .reg .u64 t; cvta.to.shared.u64 t, %1; cvt.u32.u64 %0, t; }" : "=r"(a) : "l"(p));
    return a;
}
__device__ __forceinline__ uint32_t pack_h2(float lo, float hi) {
    __half2 h = __floats2half2_rn(lo, hi);
    return *reinterpret_cast<uint32_t*>(&h);
}
__device__ __forceinline__ uint32_t sw64(uint32_t o) { return o ^ ((o >> 3) & 0x30); }

#define MBARRIER_INIT(a, c) \
    asm volatile("mbarrier.init.shared.b64 [%0], %1;" :: "r"(a), "r"(c) : "memory")
#define MBARRIER_ARRIVE(a) \
    asm volatile("mbarrier.arrive.shared.b64 _, [%0];" :: "r"(a) : "memory")
#define MBARRIER_WAIT_PARITY(mbar_addr, phase_parity) do {                         \
    uint32_t _mbar = (uint32_t)(mbar_addr);                                        \
    uint32_t _par  = (uint32_t)(phase_parity);                                     \
    uint32_t _done;                                                                \
    asm volatile("{\n\t.reg .pred p;\n\t"                                          \
        "mbarrier.try_wait.parity.shared.b64 p, [%1], %2;\n\t"                     \
        "selp.b32 %0, 1, 0, p;\n\t}"                                               \
        : "=r"(_done) : "r"(_mbar), "r"(_par) : "memory");                         \
    if (!_done) {                                                                  \
        asm volatile("{\n\t.reg .pred P1;\n\t"                                     \
            "WAIT_LOOP_%=:\n\t"                                                    \
            "mbarrier.try_wait.parity.shared.b64 P1, [%0], %1;\n\t"                \
            "@P1 bra.uni WAIT_DONE_%=;\n\t"                                        \
            "bra.uni WAIT_LOOP_%=;\n\t"                                            \
            "WAIT_DONE_%=:\n\t}"                                                   \
            :: "r"(_mbar), "r"(_par) : "memory");                                  \
    }                                                                              \
} while (0)

__device__ __forceinline__ void cons_bar() {
    asm volatile("bar.sync 1, %0;" :: "r"(NCONS) : "memory");
}
__device__ __forceinline__ void ldsm4(uint32_t* r, uint32_t a) {
    asm volatile("ldmatrix.sync.aligned.m8n8.x4.shared.b16 {%0,%1,%2,%3}, [%4];"
                 : "=r"(r[0]), "=r"(r[1]), "=r"(r[2]), "=r"(r[3]) : "r"(a));
}
__device__ __forceinline__ void ldsm2(uint32_t* r, uint32_t a) {
    asm volatile("ldmatrix.sync.aligned.m8n8.x2.shared.b16 {%0,%1}, [%2];"
                 : "=r"(r[0]), "=r"(r[1]) : "r"(a));
}
__device__ __forceinline__ void mma16(float* c, const uint32_t* a, const uint32_t* b) {
    asm volatile("mma.sync.aligned.m16n8k16.row.col.f32.f16.f16.f32 "
                 "{%0,%1,%2,%3}, {%4,%5,%6,%7}, {%8,%9}, {%0,%1,%2,%3};"
                 : "+f"(c[0]), "+f"(c[1]), "+f"(c[2]), "+f"(c[3])
                 : "r"(a[0]), "r"(a[1]), "r"(a[2]), "r"(a[3]), "r"(b[0]), "r"(b[1]));
}

// Warp-specialized persistent GEMM. Per l: Y[o,n] = sum_i W[o,i]*X[n,i].
// 12 consumer warps (4M x 3N) do ldsm+mma+epilogue only; 4 producer warps do
// LDG + f32->f16 convert + swizzled STS into a 6-slot ring of B chunk buffers.
// Slot handoff via mbarriers (full: 128 arrivals, empty: 384 arrivals); the
// mainloop has NO CTA-wide barriers, so consumers free-run up to ring depth
// and producers absorb all DRAM latency.
template <int D, int BT>
__device__ __forceinline__ void run_range(
    const float* __restrict__ x, const float* __restrict__ W,
    const float* __restrict__ bias, float* __restrict__ out,
    int off_l, int lo, int hi)
{
    constexpr int NT  = BT * D;          // multiple of 24; WN multiple of 8
    constexpr int WN  = NT / 3;
    constexpr int NF  = WN / 8;
    constexpr int F4  = NT * 8;          // float4 loads per chunk
    constexpr int HB  = BT / 2;          // batches per epilogue pass (EPASS=2)
    constexpr int ERS = 128 * D + 4;     // epi row stride (floats), +4 pad
    constexpr int ER4 = 32 * D + 1;

    const int cta = blockIdx.x;
    int rr = (cta - lo) % GRID; if (rr < 0) rr += GRID;
    const int start = lo + rr;
    if (start >= hi) return;             // uniform per CTA

    extern __shared__ char smem[];
    char*  As    = smem;
    char*  slots = smem + SLOTS_OFF;
    float* epi   = reinterpret_cast<float*>(smem + EPI_OFF);

    const int tid  = threadIdx.x;
    const int lane = tid & 31;
    const int wid  = tid >> 5;
    const int m0   = (cta & 1) * 128;

    const uint32_t sb      = smem_u32(smem);
    const uint32_t mbar    = sb + MBAR_OFF;          // full[s]=+16s, empty[s]=+16s+8
    const uint32_t slots_u = sb + SLOTS_OFF;

    __syncthreads();   // previous range fully quiesced (smem + mbarriers)
    if (tid == 0) {
#pragma unroll
        for (int s = 0; s < NSLOTS; s++) {
            MBARRIER_INIT(mbar + s * 16,     128);   // full: producer threads
            MBARRIER_INIT(mbar + s * 16 + 8, NCONS); // empty: consumer threads
        }
    }
    // ---- preload W tile (128 x 256) as fp16, SW64, 8 K-chunk sub-tiles ----
    for (int q = tid; q < 128 * 64; q += NTHREADS) {
        int r  = q >> 6;
        int cq = q & 63;
        float4 v = *reinterpret_cast<const float4*>(W + (size_t)(m0 + r) * 256 + cq * 4);
        uint2 u;
        u.x = pack_h2(v.x, v.y);
        u.y = pack_h2(v.z, v.w);
        *reinterpret_cast<uint2*>(As + (cq >> 3) * 8192 +
                                  sw64((uint32_t)(r * 64 + (cq & 7) * 8))) = u;
    }
    __syncthreads();   // publishes W tile + mbarrier init

    if (wid < 12) {
        // ================= CONSUMERS (12 warps: 4M x 3N) =================
        const int wm = wid >> 2;         // careful: want 4 M groups x 3 N groups
        const int wn = wid & 3;          // placeholder; recompute properly below
        (void)wm; (void)wn;
        const int cm = wid / 3;          // 0..3  (32-row M groups)
        const int cn = wid % 3;          // 0..2  (WN-col N groups)
        const int a_rowb = cm * 32 + ((lane >> 3) & 1) * 8 + (lane & 7);
        const int a_col  = ((lane >> 4) & 1) * 16;
        const int b_rowb = cn * WN + ((lane >> 4) & 1) * 8 + (lane & 7);
        const int b_col  = ((lane >> 3) & 1) * 16;
        const int b2_row = cn * WN + (NF - 1) * 8 + (lane & 7);

        float acc[2][NF][4];
        int s = 0, ph = 0;

        for (int it = start; it < hi; it += GRID) {
            const int b0 = ((it - lo) >> 1) * BT;
#pragma unroll
            for (int fm = 0; fm < 2; fm++)
#pragma unroll
                for (int fn = 0; fn < NF; fn++)
#pragma unroll
                    for (int e = 0; e < 4; e++) acc[fm][fn][e] = 0.0f;

#pragma unroll 1
            for (int kc = 0; kc < 8; kc++) {
                MBARRIER_WAIT_PARITY(mbar + s * 16, ph);  // full[s]
                const uint32_t Ac = sb + kc * 8192;
                const uint32_t Bc = slots_u + s * SLOT_BSZ;
#pragma unroll
                for (int ks = 0; ks < 2; ks++) {
                    uint32_t bfr[NF][2];
#pragma unroll
                    for (int q2 = 0; q2 < NF / 2; q2++) {
                        uint32_t t[4];
                        ldsm4(t, Bc + sw64((uint32_t)((b_rowb + q2 * 16) * 64 +
                                                      ks * 32 + b_col)));
                        bfr[2 * q2][0] = t[0]; bfr[2 * q2][1] = t[1];
                        bfr[2 * q2 + 1][0] = t[2]; bfr[2 * q2 + 1][1] = t[3];
                    }
                    if (NF & 1) {
                        ldsm2(bfr[NF - 1], Bc + sw64((uint32_t)(b2_row * 64 +
                                                                ks * 32 + b_col)));
                    }
                    uint32_t af[2][4];
#pragma unroll
                    for (int fm = 0; fm < 2; fm++)
                        ldsm4(af[fm], Ac + sw64((uint32_t)((a_rowb + fm * 16) * 64 +
                                                           ks * 32 + a_col)));
#pragma unroll
                    for (int fm = 0; fm < 2; fm++)
#pragma unroll
                        for (int fn = 0; fn < NF; fn++)
                            mma16(acc[fm][fn], af[fm], bfr[fn]);
                }
                MBARRIER_ARRIVE(mbar + s * 16 + 8);       // empty[s]
                if (++s == NSLOTS) { s = 0; ph ^= 1; }
            }

            // ---- epilogue: 2 passes, consumer-only barrier ----
#pragma unroll 1
            for (int p = 0; p < 2; p++) {
                const int lob = p * HB, hib = lob + HB;
#pragma unroll
                for (int fm = 0; fm < 2; fm++) {
                    int m = cm * 32 + fm * 16 + (lane >> 2);
#pragma unroll
                    for (int fn = 0; fn < NF; fn++) {
                        const float* c = acc[fm][fn];
                        int n0  = cn * WN + fn * 8 + (lane & 3) * 2;
                        int n1  = n0 + 1;
                        int bb0 = n0 / D, dd0 = n0 - bb0 * D;
                        int bb1 = n1 / D, dd1 = n1 - bb1 * D;
                        if (bb0 >= lob && bb0 < hib) {
                            epi[(bb0 - lob) * ERS + m * D + dd0]       = c[0];
                            epi[(bb0 - lob) * ERS + (m + 8) * D + dd0] = c[2];
                        }
                        if (bb1 >= lob && bb1 < hib) {
                            epi[(bb1 - lob) * ERS + m * D + dd1]       = c[1];
                            epi[(bb1 - lob) * ERS + (m + 8) * D + dd1] = c[3];
                        }
                    }
                }
                cons_bar();

                const int base_b = b0 + lob;
                const float4* e4 = reinterpret_cast<const float4*>(epi);
                for (int q = tid; q < HB * 32 * D; q += NCONS) {
                    int bb = q / (32 * D);
                    int r  = q - bb * (32 * D);
                    int gb = base_b + bb;
                    if (gb < BATCH) {
                        float4 v = e4[(size_t)bb * ER4 + r];
                        if (D == 1) {
                            float4 bv = *reinterpret_cast<const float4*>(bias + m0 + r * 4);
                            v.x += bv.x; v.y += bv.y; v.z += bv.z; v.w += bv.w;
                        }
                        *reinterpret_cast<float4*>(
                            out + (size_t)gb * 4096 + off_l + m0 * D + r * 4) = v;
                    }
                }
                cons_bar();   // epi region reused by next pass / next tile
            }
        }
    } else {
        // ================= PRODUCERS (4 warps, 128 threads) =================
        const int ptid = tid - NCONS;
        int s = 0, ph = 1;   // parity-1 first wait passes on fresh barriers

        for (int it = start; it < hi; it += GRID) {
            const int b0 = ((it - lo) >> 1) * BT;
#pragma unroll 1
            for (int kc = 0; kc < 8; kc++) {
                MBARRIER_WAIT_PARITY(mbar + s * 16 + 8, ph);   // empty[s]
                char* dst = slots + s * SLOT_BSZ;
                const float* src0 = x + off_l + kc * (32 * D);
#pragma unroll 2
                for (int q = ptid; q < F4; q += 128) {
                    int j  = q * 4;
                    int bb = j / (32 * D);
                    int jj = j - bb * (32 * D);
                    float4 v = make_float4(0.f, 0.f, 0.f, 0.f);
                    if (b0 + bb < BATCH)
                        v = *reinterpret_cast<const float4*>(
                            src0 + (size_t)(bb + b0) * 4096 + jj);
                    if (D == 1) {
                        uint2 u;
                        u.x = pack_h2(v.x, v.y);
                        u.y = pack_h2(v.z, v.w);
                        *reinterpret_cast<uint2*>(
                            dst + sw64((uint32_t)(bb * 64 + jj * 2))) = u;
                    } else {
                        float vv[4] = {v.x, v.y, v.z, v.w};
#pragma unroll
                        for (int e = 0; e < 4; e++) {
                            int je = jj + e;
                            int i  = je / D;
                            int dd = je - i * D;
                            int n  = bb * D + dd;
                            *reinterpret_cast<__half*>(
                                dst + sw64((uint32_t)(n * 64 + i * 2))) =
                                __float2half_rn(vv[e]);
                        }
                    }
                }
                MBARRIER_ARRIVE(mbar + s * 16);                // full[s]
                if (++s == NSLOTS) { s = 0; ph ^= 1; }
            }
        }
    }
}

// Flat item ranges (all bases even; items = 2 * n_tiles):
//  l0: D=1, BT=192, NT=192, 105 tiles -> [   0,  210)
//  l1: D=3, BT=64,  NT=192, 313 tiles -> [ 210,  836)
//  l2: D=5, BT=24,  NT=120, 834 tiles -> [ 836, 2504)
//  l3: D=7, BT=24,  NT=168, 834 tiles -> [2504, 4172)
__global__ __launch_bounds__(NTHREADS, 1)
void so3_fused(const float* __restrict__ x,
               const float* __restrict__ W0, const float* __restrict__ W1,
               const float* __restrict__ W2, const float* __restrict__ W3,
               const float* __restrict__ bias, float* __restrict__ out)
{
    run_range<1, 192>(x, W0, bias, out, 0,       0,  210);
    run_range<3,  64>(x, W1, bias, out, 256,   210,  836);
    run_range<5,  24>(x, W2, bias, out, 1024,  836, 2504);
    run_range<7,  24>(x, W3, bias, out, 2304, 2504, 4172);
}

extern "C" void kernel_launch(void* const* d_in, const int* in_sizes, int n_in,
                              void* d_out, int out_size) {
    const float* x    = (const float*)d_in[0];
    const float* W0   = (const float*)d_in[1];
    const float* W1   = (const float*)d_in[2];
    const float* W2   = (const float*)d_in[3];
    const float* W3   = (const float*)d_in[4];
    const float* bias = (const float*)d_in[5];
    float* out = (float*)d_out;

    cudaFuncSetAttribute(so3_fused, cudaFuncAttributeMaxDynamicSharedMemorySize,
                         SMEM_BYTES);
    so3_fused<<<GRID, NTHREADS, SMEM_BYTES>>>(x, W0, W1, W2, W3, bias, out);
}

// round 13
// speedup vs baseline: 2.8308x; 2.8308x over previous
#include <cuda_runtime.h>
#include <cuda_fp16.h>
#include <cstdint>

static constexpr int BATCH   = 20000;
static constexpr int A_BYTES = 65536;    // 8 K-chunks x 128 rows x 64B fp16 W tile
static constexpr int GRID    = 152;      // one persistent CTA per SM
static constexpr int SMEM_BYTES = 151808;  // max range (l3): A + 2*14336 + 57600

__device__ __forceinline__ uint32_t smem_u32(const void* p) {
    uint32_t a;
    asm("{ .reg .u64 t; cvta.to.shared.u64 t, %1; cvt.u32.u64 %0, t; }" : "=r"(a) : "l"(p));
    return a;
}
__device__ __forceinline__ uint32_t pack_h2(float lo, float hi) {
    __half2 h = __floats2half2_rn(lo, hi);
    return *reinterpret_cast<uint32_t*>(&h);
}
__device__ __forceinline__ uint32_t sw64(uint32_t o) { return o ^ ((o >> 3) & 0x30); }

__device__ __forceinline__ void ldsm4(uint32_t* r, uint32_t a) {
    asm volatile("ldmatrix.sync.aligned.m8n8.x4.shared.b16 {%0,%1,%2,%3}, [%4];"
                 : "=r"(r[0]), "=r"(r[1]), "=r"(r[2]), "=r"(r[3]) : "r"(a));
}
__device__ __forceinline__ void ldsm2(uint32_t* r, uint32_t a) {
    asm volatile("ldmatrix.sync.aligned.m8n8.x2.shared.b16 {%0,%1}, [%2];"
                 : "=r"(r[0]), "=r"(r[1]) : "r"(a));
}
__device__ __forceinline__ void mma16(float* c, const uint32_t* a, const uint32_t* b) {
    asm volatile("mma.sync.aligned.m16n8k16.row.col.f32.f16.f16.f32 "
                 "{%0,%1,%2,%3}, {%4,%5,%6,%7}, {%8,%9}, {%0,%1,%2,%3};"
                 : "+f"(c[0]), "+f"(c[1]), "+f"(c[2]), "+f"(c[3])
                 : "r"(a[0]), "r"(a[1]), "r"(a[2]), "r"(a[3]), "r"(b[0]), "r"(b[1]));
}

// R9 chassis (proven 300us): persistent CTA, fp16 operands / f32 accum, CTA tile
// 128 x NT, K=256 in 8 chunks of 32, SW64 rows of 64B, B double-buffered, 16
// warps as 4(M)x4(N). This round removes redundant per-chunk ALU: all index
// divisions in the B-staging path are hoisted into tile-invariant registers,
// bounds checks are compile-time eliminated where BT divides BATCH, and the
// epilogue STG loop is division-free.
template <int D, int BT, bool GUARD>
__device__ __forceinline__ void run_range(
    const float* __restrict__ x, const float* __restrict__ W,
    const float* __restrict__ bias, float* __restrict__ out,
    int off_l, int lo, int hi)
{
    constexpr int NT   = BT * D;         // multiple of 32, <= 224
    constexpr int WN   = NT / 4;         // warp n-tile
    constexpr int NF   = WN / 8;         // n8 fragments per warp
    constexpr int HB   = BT / 2;         // batches per epilogue pass
    constexpr int BSZ  = NT * 64;        // bytes per B buffer (fp16 rows)
    constexpr int F4   = NT * 8;         // float4 loads per chunk
    constexpr int SDIV = 32 * D;         // floats per batch per chunk
    constexpr int ERS  = 128 * D + 4;    // epi row stride (floats), +4 pad
    constexpr int ER4  = 32 * D + 1;     // epi row stride (float4)
    constexpr int EB   = 512 / SDIV;     // STG loop: batch step
    constexpr int ER   = 512 % SDIV;     // STG loop: r step

    const int cta = blockIdx.x;
    int rr = (cta - lo) % GRID; if (rr < 0) rr += GRID;
    const int start = lo + rr;
    if (start >= hi) return;             // uniform per CTA

    extern __shared__ char smem[];
    char*  As  = smem;
    char*  Bs  = smem + A_BYTES;
    float* epi = reinterpret_cast<float*>(smem + A_BYTES + 2 * BSZ);

    const int tid  = threadIdx.x;
    const int lane = tid & 31;
    const int wid  = tid >> 5;
    const int wm   = wid >> 2;
    const int wn   = wid & 3;
    const int m0   = (cta & 1) * 128;

    __syncthreads();   // previous range fully done with SMEM
    // ---- preload W tile (128 x 256) as fp16, SW64, 8 K-chunk sub-tiles ----
    for (int q = tid; q < 128 * 64; q += 512) {
        int r  = q >> 6;
        int cq = q & 63;
        float4 v = *reinterpret_cast<const float4*>(W + (size_t)(m0 + r) * 256 + cq * 4);
        uint2 u;
        u.x = pack_h2(v.x, v.y);
        u.y = pack_h2(v.z, v.w);
        *reinterpret_cast<uint2*>(As + (cq >> 3) * 8192 +
                                  sw64((uint32_t)(r * 64 + (cq & 7) * 8))) = u;
    }

    const int a_rowb = wm * 32 + ((lane >> 3) & 1) * 8 + (lane & 7);
    const int a_col  = ((lane >> 4) & 1) * 16;
    const int b_rowb = wn * WN + ((lane >> 4) & 1) * 8 + (lane & 7);
    const int b_col  = ((lane >> 3) & 1) * 16;
    const int b2_row = wn * WN + (NF - 1) * 8 + (lane & 7);
    const uint32_t As_u = smem_u32(smem);
    const uint32_t Bs_u = As_u + A_BYTES;

    // ---- tile-invariant B-staging precompute (replaces per-chunk div/mod) ----
    bool     val_h[4];
    int      bb_h[4];          // batch within tile
    int      ldg_h[4];         // bb*4096 + jj  (float offset from batch base)
    uint32_t st1_h[4];         // D==1: full swizzled STS address offset
    int      n0_h[4], i0_h[4], dd0_h[4];   // D>1: scatter seeds
#pragma unroll
    for (int h = 0; h < 4; h++) {
        int q = tid + h * 512;
        val_h[h] = (q < F4);
        int j  = q * 4;
        int bb = j / SDIV;
        int jj = j - bb * SDIV;
        bb_h[h]  = bb;
        ldg_h[h] = bb * 4096 + jj;
        if (D == 1) {
            st1_h[h] = sw64((uint32_t)(bb * 64 + jj * 2));
        } else {
            int i0 = jj / D;
            dd0_h[h] = jj - i0 * D;
            i0_h[h]  = i0;
            n0_h[h]  = bb * D + dd0_h[h];
        }
    }

    float acc[2][NF][4];
    float4 hold[4];

    auto ldgB = [&](int b0, int kc) {
        const float* src0 = x + off_l + kc * SDIV + (size_t)b0 * 4096;
#pragma unroll
        for (int h = 0; h < 4; h++) {
            hold[h] = make_float4(0.f, 0.f, 0.f, 0.f);
            if (val_h[h] && (!GUARD || b0 + bb_h[h] < BATCH))
                hold[h] = *reinterpret_cast<const float4*>(src0 + ldg_h[h]);
        }
    };
    auto stsB = [&](int buf) {
        char* dst = Bs + buf * BSZ;
#pragma unroll
        for (int h = 0; h < 4; h++) {
            if (val_h[h]) {
                if (D == 1) {
                    uint2 u;
                    u.x = pack_h2(hold[h].x, hold[h].y);
                    u.y = pack_h2(hold[h].z, hold[h].w);
                    *reinterpret_cast<uint2*>(dst + st1_h[h]) = u;
                } else {
                    float vv[4] = {hold[h].x, hold[h].y, hold[h].z, hold[h].w};
                    int i = i0_h[h], n = n0_h[h], dd = dd0_h[h];
#pragma unroll
                    for (int e = 0; e < 4; e++) {
                        *reinterpret_cast<__half*>(
                            dst + sw64((uint32_t)(n * 64 + i * 2))) =
                            __float2half_rn(vv[e]);
                        if (++dd == D) { dd = 0; i++; n -= (D - 1); }
                        else           { n++; }
                    }
                }
            }
        }
    };

    ldgB(((start - lo) >> 1) * BT, 0);   // first tile, chunk 0

    for (int it = start; it < hi; it += GRID) {
        const int b0 = ((it - lo) >> 1) * BT;

#pragma unroll
        for (int fm = 0; fm < 2; fm++)
#pragma unroll
            for (int fn = 0; fn < NF; fn++)
#pragma unroll
                for (int e = 0; e < 4; e++) acc[fm][fn][e] = 0.0f;

        stsB(0);          // chunk 0 (held since previous tile / pre-loop)
        __syncthreads();  // also covers W-tile publication on first iteration

#pragma unroll 1
        for (int kc = 0; kc < 8; kc++) {
            if (kc < 7) ldgB(b0, kc + 1);
            else if (it + GRID < hi) ldgB(((it + GRID - lo) >> 1) * BT, 0);
            const uint32_t Ac = As_u + kc * 8192;
            const uint32_t Bc = Bs_u + (kc & 1) * BSZ;
#pragma unroll
            for (int ks = 0; ks < 2; ks++) {
                uint32_t bfr[NF][2];
#pragma unroll
                for (int q2 = 0; q2 < NF / 2; q2++) {
                    uint32_t t[4];
                    ldsm4(t, Bc + sw64((uint32_t)((b_rowb + q2 * 16) * 64 +
                                                  ks * 32 + b_col)));
                    bfr[2 * q2][0] = t[0]; bfr[2 * q2][1] = t[1];
                    bfr[2 * q2 + 1][0] = t[2]; bfr[2 * q2 + 1][1] = t[3];
                }
                if (NF & 1) {
                    ldsm2(bfr[NF - 1], Bc + sw64((uint32_t)(b2_row * 64 +
                                                            ks * 32 + b_col)));
                }
                uint32_t af[2][4];
#pragma unroll
                for (int fm = 0; fm < 2; fm++)
                    ldsm4(af[fm], Ac + sw64((uint32_t)((a_rowb + fm * 16) * 64 +
                                                       ks * 32 + a_col)));
#pragma unroll
                for (int fm = 0; fm < 2; fm++)
#pragma unroll
                    for (int fn = 0; fn < NF; fn++)
                        mma16(acc[fm][fn], af[fm], bfr[fn]);
            }
            if (kc < 7) stsB((kc + 1) & 1);
            __syncthreads();
        }

        // ---- epilogue: 2 passes staged through padded f32 SMEM region ----
#pragma unroll 1
        for (int p = 0; p < 2; p++) {
            if ((wn >> 1) == p) {
#pragma unroll
                for (int fm = 0; fm < 2; fm++) {
                    int m = wm * 32 + fm * 16 + (lane >> 2);
#pragma unroll
                    for (int fn = 0; fn < NF; fn++) {
                        const float* c = acc[fm][fn];
                        int n0  = (wn & 1) * WN + fn * 8 + (lane & 3) * 2;
                        int n1  = n0 + 1;
                        int bb0 = n0 / D, dd0 = n0 - bb0 * D;
                        int bb1 = n1 / D, dd1 = n1 - bb1 * D;
                        epi[bb0 * ERS + m * D + dd0]       = c[0];
                        epi[bb1 * ERS + m * D + dd1]       = c[1];
                        epi[bb0 * ERS + (m + 8) * D + dd0] = c[2];
                        epi[bb1 * ERS + (m + 8) * D + dd1] = c[3];
                    }
                }
            }
            __syncthreads();

            const int base_b = b0 + p * HB;
            const float4* e4 = reinterpret_cast<const float4*>(epi);
            {
                int bb = tid / SDIV;          // float4-count per batch == SDIV
                int r  = tid - bb * SDIV;
                for (int q = tid; q < HB * SDIV; q += 512) {
                    int gb = base_b + bb;
                    if (!GUARD || gb < BATCH) {
                        float4 v = e4[(size_t)bb * ER4 + r];
                        if (D == 1) {
                            float4 bv = *reinterpret_cast<const float4*>(bias + m0 + r * 4);
                            v.x += bv.x; v.y += bv.y; v.z += bv.z; v.w += bv.w;
                        }
                        *reinterpret_cast<float4*>(
                            out + (size_t)gb * 4096 + off_l + m0 * D + r * 4) = v;
                    }
                    bb += EB; r += ER;
                    if (ER != 0 && r >= SDIV) { r -= SDIV; bb++; }
                }
            }
            __syncthreads();
        }
    }
}

// Flat item ranges (all bases even; items = 2 * n_tiles):
//  l0: D=1, BT=160, 125 tiles (exact)  -> [   0,  250)  GUARD=false
//  l1: D=3, BT=64,  313 tiles (312.5)  -> [ 250,  876)  GUARD=true
//  l2: D=5, BT=32,  625 tiles (exact)  -> [ 876, 2126)  GUARD=false
//  l3: D=7, BT=32,  625 tiles (exact)  -> [2126, 3376)  GUARD=false
__global__ __launch_bounds__(512, 1)
void so3_fused(const float* __restrict__ x,
               const float* __restrict__ W0, const float* __restrict__ W1,
               const float* __restrict__ W2, const float* __restrict__ W3,
               const float* __restrict__ bias, float* __restrict__ out)
{
    run_range<1, 160, false>(x, W0, bias, out, 0,       0,  250);
    run_range<3,  64, true >(x, W1, bias, out, 256,   250,  876);
    run_range<5,  32, false>(x, W2, bias, out, 1024,  876, 2126);
    run_range<7,  32, false>(x, W3, bias, out, 2304, 2126, 3376);
}

extern "C" void kernel_launch(void* const* d_in, const int* in_sizes, int n_in,
                              void* d_out, int out_size) {
    const float* x    = (const float*)d_in[0];
    const float* W0   = (const float*)d_in[1];
    const float* W1   = (const float*)d_in[2];
    const float* W2   = (const float*)d_in[3];
    const float* W3   = (const float*)d_in[4];
    const float* bias = (const float*)d_in[5];
    float* out = (float*)d_out;

    cudaFuncSetAttribute(so3_fused, cudaFuncAttributeMaxDynamicSharedMemorySize,
                         SMEM_BYTES);
    so3_fused<<<GRID, 512, SMEM_BYTES>>>(x, W0, W1, W2, W3, bias, out);
}

// round 14
// speedup vs baseline: 3.3002x; 1.1658x over previous
#include <cuda_runtime.h>
#include <cuda_fp16.h>
#include <cstdint>

static constexpr int BATCH   = 20000;
static constexpr int A_BYTES = 131072;   // 8 K-chunks x 256 rows x 64B fp16 W tile
static constexpr int GRID    = 152;      // one persistent CTA per SM
static constexpr int SMEM_BYTES = 203648;  // max range (l0): A + 2*7168 + 58240

__device__ __forceinline__ uint32_t smem_u32(const void* p) {
    uint32_t a;
    asm("{ .reg .u64 t; cvta.to.shared.u64 t, %1; cvt.u32.u64 %0, t; }" : "=r"(a) : "l"(p));
    return a;
}
__device__ __forceinline__ uint32_t pack_h2(float lo, float hi) {
    __half2 h = __floats2half2_rn(lo, hi);
    return *reinterpret_cast<uint32_t*>(&h);
}
__device__ __forceinline__ uint32_t sw64(uint32_t o) { return o ^ ((o >> 3) & 0x30); }

__device__ __forceinline__ void ldsm4(uint32_t* r, uint32_t a) {
    asm volatile("ldmatrix.sync.aligned.m8n8.x4.shared.b16 {%0,%1,%2,%3}, [%4];"
                 : "=r"(r[0]), "=r"(r[1]), "=r"(r[2]), "=r"(r[3]) : "r"(a));
}
__device__ __forceinline__ void ldsm2(uint32_t* r, uint32_t a) {
    asm volatile("ldmatrix.sync.aligned.m8n8.x2.shared.b16 {%0,%1}, [%2];"
                 : "=r"(r[0]), "=r"(r[1]) : "r"(a));
}
__device__ __forceinline__ void mma16(float* c, const uint32_t* a, const uint32_t* b) {
    asm volatile("mma.sync.aligned.m16n8k16.row.col.f32.f16.f16.f32 "
                 "{%0,%1,%2,%3}, {%4,%5,%6,%7}, {%8,%9}, {%0,%1,%2,%3};"
                 : "+f"(c[0]), "+f"(c[1]), "+f"(c[2]), "+f"(c[3])
                 : "r"(a[0]), "r"(a[1]), "r"(a[2]), "r"(a[3]), "r"(b[0]), "r"(b[1]));
}

// Per l: Y[o,n] = sum_i W[o,i]*X[n,i]. M=256 per CTA (FULL output column): each
// batch tile is owned by exactly one CTA, so x is LDG'd, converted and staged
// to SMEM exactly ONCE chip-wide (R13 staged it twice via M-parity pairs).
// Persistent CTA, fp16 operands / f32 accum, K=256 in 8 chunks of 32, SW64
// rows of 64B, B double-buffered, R9/R13 dataflow. 16 warps as 8(M) x 2(N).
// Epilogue: 2 batch-half passes; pass p is written entirely by warps wn==p.
template <int D, int BT, bool GUARD>
__device__ __forceinline__ void run_range(
    const float* __restrict__ x, const float* __restrict__ W,
    const float* __restrict__ bias, float* __restrict__ out,
    int off_l, int lo, int hi)
{
    constexpr int NT   = BT * D;         // multiple of 16
    constexpr int WN   = NT / 2;         // warp n-tile (multiple of 8)
    constexpr int NF   = WN / 8;         // n8 fragments per warp (<= 7)
    constexpr int HB   = BT / 2;         // batches per epilogue pass
    constexpr int BSZ  = NT * 64;        // bytes per B buffer (fp16 rows)
    constexpr int F4   = NT * 8;         // float4 loads per chunk
    constexpr int SDIV = 32 * D;         // x float4s per batch per chunk
    constexpr int ERS  = 256 * D + 4;    // epi row stride (floats), +4 pad
    constexpr int ER4  = 64 * D + 1;     // epi row stride (float4)
    constexpr int ODIV = 64 * D;         // out float4s per batch
    constexpr int EB   = 512 / ODIV;     // STG loop: batch step
    constexpr int ER   = 512 % ODIV;     // STG loop: r step

    const int cta = blockIdx.x;
    int rr = (cta - lo) % GRID; if (rr < 0) rr += GRID;
    const int start = lo + rr;
    if (start >= hi) return;             // uniform per CTA

    extern __shared__ char smem[];
    char*  As  = smem;
    char*  Bs  = smem + A_BYTES;
    float* epi = reinterpret_cast<float*>(smem + A_BYTES + 2 * BSZ);

    const int tid  = threadIdx.x;
    const int lane = tid & 31;
    const int wid  = tid >> 5;
    const int wm   = wid >> 1;           // 0..7  (32-row M groups)
    const int wn   = wid & 1;            // 0..1  (WN-col N groups)

    __syncthreads();   // previous range fully done with SMEM
    // ---- preload W tile (256 x 256) as fp16, SW64, 8 K-chunk sub-tiles ----
    for (int q = tid; q < 256 * 64; q += 512) {
        int r  = q >> 6;
        int cq = q & 63;
        float4 v = *reinterpret_cast<const float4*>(W + (size_t)r * 256 + cq * 4);
        uint2 u;
        u.x = pack_h2(v.x, v.y);
        u.y = pack_h2(v.z, v.w);
        *reinterpret_cast<uint2*>(As + (cq >> 3) * 16384 +
                                  sw64((uint32_t)(r * 64 + (cq & 7) * 8))) = u;
    }

    const int a_rowb = wm * 32 + ((lane >> 3) & 1) * 8 + (lane & 7);
    const int a_col  = ((lane >> 4) & 1) * 16;
    const int b_rowb = wn * WN + ((lane >> 4) & 1) * 8 + (lane & 7);
    const int b_col  = ((lane >> 3) & 1) * 16;
    const int b2_row = wn * WN + (NF - 1) * 8 + (lane & 7);
    const uint32_t As_u = smem_u32(smem);
    const uint32_t Bs_u = As_u + A_BYTES;

    // ---- tile-invariant B-staging precompute (no per-chunk div/mod) ----
    bool     val_h[2];
    int      bb_h[2];
    int      ldg_h[2];          // bb*4096 + jj (float offset from batch base)
    uint32_t st1_h[2];          // D==1: swizzled STS offset
    int      n0_h[2], i0_h[2], dd0_h[2];
#pragma unroll
    for (int h = 0; h < 2; h++) {
        int q = tid + h * 512;
        val_h[h] = (q < F4);
        int j  = q * 4;
        int bb = j / SDIV;
        int jj = j - bb * SDIV;
        bb_h[h]  = bb;
        ldg_h[h] = bb * 4096 + jj;
        if (D == 1) {
            st1_h[h] = sw64((uint32_t)(bb * 64 + jj * 2));
        } else {
            int i0 = jj / D;
            dd0_h[h] = jj - i0 * D;
            i0_h[h]  = i0;
            n0_h[h]  = bb * D + dd0_h[h];
        }
    }

    float acc[2][NF][4];
    float4 hold[2];

    auto ldgB = [&](int b0, int kc) {
        const float* src0 = x + off_l + kc * SDIV + (size_t)b0 * 4096;
#pragma unroll
        for (int h = 0; h < 2; h++) {
            hold[h] = make_float4(0.f, 0.f, 0.f, 0.f);
            if (val_h[h] && (!GUARD || b0 + bb_h[h] < BATCH))
                hold[h] = *reinterpret_cast<const float4*>(src0 + ldg_h[h]);
        }
    };
    auto stsB = [&](int buf) {
        char* dst = Bs + buf * BSZ;
#pragma unroll
        for (int h = 0; h < 2; h++) {
            if (val_h[h]) {
                if (D == 1) {
                    uint2 u;
                    u.x = pack_h2(hold[h].x, hold[h].y);
                    u.y = pack_h2(hold[h].z, hold[h].w);
                    *reinterpret_cast<uint2*>(dst + st1_h[h]) = u;
                } else {
                    float vv[4] = {hold[h].x, hold[h].y, hold[h].z, hold[h].w};
                    int i = i0_h[h], n = n0_h[h], dd = dd0_h[h];
#pragma unroll
                    for (int e = 0; e < 4; e++) {
                        *reinterpret_cast<__half*>(
                            dst + sw64((uint32_t)(n * 64 + i * 2))) =
                            __float2half_rn(vv[e]);
                        if (++dd == D) { dd = 0; i++; n -= (D - 1); }
                        else           { n++; }
                    }
                }
            }
        }
    };

    ldgB((start - lo) * BT, 0);   // first tile, chunk 0

    for (int it = start; it < hi; it += GRID) {
        const int b0 = (it - lo) * BT;

#pragma unroll
        for (int fm = 0; fm < 2; fm++)
#pragma unroll
            for (int fn = 0; fn < NF; fn++)
#pragma unroll
                for (int e = 0; e < 4; e++) acc[fm][fn][e] = 0.0f;

        stsB(0);          // chunk 0 (held since previous tile / pre-loop)
        __syncthreads();  // also covers W-tile publication on first iteration

#pragma unroll 1
        for (int kc = 0; kc < 8; kc++) {
            if (kc < 7) ldgB(b0, kc + 1);
            else if (it + GRID < hi) ldgB((it + GRID - lo) * BT, 0);
            const uint32_t Ac = As_u + kc * 16384;
            const uint32_t Bc = Bs_u + (kc & 1) * BSZ;
#pragma unroll
            for (int ks = 0; ks < 2; ks++) {
                uint32_t bfr[NF][2];
#pragma unroll
                for (int q2 = 0; q2 < NF / 2; q2++) {
                    uint32_t t[4];
                    ldsm4(t, Bc + sw64((uint32_t)((b_rowb + q2 * 16) * 64 +
                                                  ks * 32 + b_col)));
                    bfr[2 * q2][0] = t[0]; bfr[2 * q2][1] = t[1];
                    bfr[2 * q2 + 1][0] = t[2]; bfr[2 * q2 + 1][1] = t[3];
                }
                if (NF & 1) {
                    ldsm2(bfr[NF - 1], Bc + sw64((uint32_t)(b2_row * 64 +
                                                            ks * 32 + b_col)));
                }
                uint32_t af[2][4];
#pragma unroll
                for (int fm = 0; fm < 2; fm++)
                    ldsm4(af[fm], Ac + sw64((uint32_t)((a_rowb + fm * 16) * 64 +
                                                       ks * 32 + a_col)));
#pragma unroll
                for (int fm = 0; fm < 2; fm++)
#pragma unroll
                    for (int fn = 0; fn < NF; fn++)
                        mma16(acc[fm][fn], af[fm], bfr[fn]);
            }
            if (kc < 7) stsB((kc + 1) & 1);
            __syncthreads();
        }

        // ---- epilogue: 2 batch-half passes; warps wn==p own pass p ----
#pragma unroll 1
        for (int p = 0; p < 2; p++) {
            if (wn == p) {
#pragma unroll
                for (int fm = 0; fm < 2; fm++) {
                    int m = wm * 32 + fm * 16 + (lane >> 2);
#pragma unroll
                    for (int fn = 0; fn < NF; fn++) {
                        const float* c = acc[fm][fn];
                        int n0  = fn * 8 + (lane & 3) * 2;   // local to this pass
                        int n1  = n0 + 1;
                        int bb0 = n0 / D, dd0 = n0 - bb0 * D;
                        int bb1 = n1 / D, dd1 = n1 - bb1 * D;
                        epi[bb0 * ERS + m * D + dd0]       = c[0];
                        epi[bb1 * ERS + m * D + dd1]       = c[1];
                        epi[bb0 * ERS + (m + 8) * D + dd0] = c[2];
                        epi[bb1 * ERS + (m + 8) * D + dd1] = c[3];
                    }
                }
            }
            __syncthreads();

            const int base_b = b0 + p * HB;
            const float4* e4 = reinterpret_cast<const float4*>(epi);
            {
                int bb = tid / ODIV;
                int r  = tid - bb * ODIV;
                for (int q = tid; q < HB * ODIV; q += 512) {
                    int gb = base_b + bb;
                    if (!GUARD || gb < BATCH) {
                        float4 v = e4[(size_t)bb * ER4 + r];
                        if (D == 1) {
                            float4 bv = *reinterpret_cast<const float4*>(bias + r * 4);
                            v.x += bv.x; v.y += bv.y; v.z += bv.z; v.w += bv.w;
                        }
                        *reinterpret_cast<float4*>(
                            out + (size_t)gb * 4096 + off_l + r * 4) = v;
                    }
                    bb += EB; r += ER;
                    if (ER != 0 && r >= ODIV) { r -= ODIV; bb++; }
                }
            }
            __syncthreads();
        }
    }
}

// Flat item ranges (item == batch tile; M=256 per CTA):
//  l0: D=1, BT=112, NT=112, 179 tiles -> [   0,  179)  GUARD=true
//  l1: D=3, BT=32,  NT=96,  625 tiles -> [ 179,  804)  GUARD=false
//  l2: D=5, BT=16,  NT=80, 1250 tiles -> [ 804, 2054)  GUARD=false
//  l3: D=7, BT=16,  NT=112,1250 tiles -> [2054, 3304)  GUARD=false
__global__ __launch_bounds__(512, 1)
void so3_fused(const float* __restrict__ x,
               const float* __restrict__ W0, const float* __restrict__ W1,
               const float* __restrict__ W2, const float* __restrict__ W3,
               const float* __restrict__ bias, float* __restrict__ out)
{
    run_range<1, 112, true >(x, W0, bias, out, 0,       0,  179);
    run_range<3,  32, false>(x, W1, bias, out, 256,   179,  804);
    run_range<5,  16, false>(x, W2, bias, out, 1024,  804, 2054);
    run_range<7,  16, false>(x, W3, bias, out, 2304, 2054, 3304);
}

extern "C" void kernel_launch(void* const* d_in, const int* in_sizes, int n_in,
                              void* d_out, int out_size) {
    const float* x    = (const float*)d_in[0];
    const float* W0   = (const float*)d_in[1];
    const float* W1   = (const float*)d_in[2];
    const float* W2   = (const float*)d_in[3];
    const float* W3   = (const float*)d_in[4];
    const float* bias = (const float*)d_in[5];
    float* out = (float*)d_out;

    cudaFuncSetAttribute(so3_fused, cudaFuncAttributeMaxDynamicSharedMemorySize,
                         SMEM_BYTES);
    so3_fused<<<GRID, 512, SMEM_BYTES>>>(x, W0, W1, W2, W3, bias, out);
}